// round 2
// baseline (speedup 1.0000x reference)
#include <cuda_runtime.h>
#include <math.h>

#define NQ 6
#define NL 4
#define NA 4
#define PRE 64
#define NS 64

typedef unsigned long long u64;

// ---- f32x2 packed-math helpers (Blackwell FFMA2 path, PTX-only) ----------
__device__ __forceinline__ u64 pk(float lo_, float hi_) {
    u64 r; asm("mov.b64 %0, {%1, %2};" : "=l"(r) : "f"(lo_), "f"(hi_)); return r;
}
__device__ __forceinline__ float f2lo(u64 v) {
    float a, b; asm("mov.b64 {%0, %1}, %2;" : "=f"(a), "=f"(b) : "l"(v)); return a;
}
__device__ __forceinline__ float f2hi(u64 v) {
    float a, b; asm("mov.b64 {%0, %1}, %2;" : "=f"(a), "=f"(b) : "l"(v)); return b;
}
__device__ __forceinline__ u64 fma2(u64 a, u64 b, u64 c) {
    u64 d; asm("fma.rn.f32x2 %0, %1, %2, %3;" : "=l"(d) : "l"(a), "l"(b), "l"(c)); return d;
}
__device__ __forceinline__ u64 mul2(u64 a, u64 b) {
    u64 d; asm("mul.rn.f32x2 %0, %1, %2;" : "=l"(d) : "l"(a), "l"(b)); return d;
}
__device__ __forceinline__ u64 add2(u64 a, u64 b) {
    u64 d; asm("add.rn.f32x2 %0, %1, %2;" : "=l"(d) : "l"(a), "l"(b)); return d;
}

// Two RY butterflies sharing one rotation, packed into f32x2 lanes.
// (a0,a1) and (b0,b1) are the two butterflies.
__device__ __forceinline__ void bfly2(u64 C, u64 S, u64 NSg,
                                      float &a0, float &a1,
                                      float &b0, float &b1) {
    u64 A = pk(a0, b0);
    u64 B = pk(a1, b1);
    u64 r0 = fma2(C, A, mul2(NSg, B));   // c*a0 - s*a1
    u64 r1 = fma2(S, A, mul2(C, B));     // s*a0 + c*a1
    asm("mov.b64 {%0, %1}, %2;" : "=f"(a0), "=f"(b0) : "l"(r0));
    asm("mov.b64 {%0, %1}, %2;" : "=f"(a1), "=f"(b1) : "l"(r1));
}

__global__ void __launch_bounds__(128) qpolicy_kernel(
    const float* __restrict__ x,
    const float* __restrict__ W1, const float* __restrict__ b1,
    const float* __restrict__ W2, const float* __restrict__ b2,
    const float* __restrict__ qw,
    const float* __restrict__ Wp, const float* __restrict__ bp,
    const float* __restrict__ Wv, const float* __restrict__ bv,
    float* __restrict__ out_policy, float* __restrict__ out_value,
    int B)
{
    // Packed weight layouts (8B-aligned so LDS.64 works)
    __shared__ __align__(8) float sW1p[32 * NQ * 2];  // [(k2*6+q)*2 + h] = W1[(2k2+h)*6+q]
    __shared__ __align__(8) float sb1[PRE];           // pairs contiguous
    __shared__ __align__(8) float sW2[NQ * PRE];      // row-major: k-pairs contiguous
    __shared__ float sb2[NQ];
    __shared__ __align__(8) float sqC[NL * NQ * 2];   // (c,c)
    __shared__ __align__(8) float sqS[NL * NQ * 2];   // (s,s)
    __shared__ __align__(8) float sqN[NL * NQ * 2];   // (-s,-s)
    __shared__ float sWp[NA * NQ];
    __shared__ float sbp[NA];
    __shared__ float sWv[NQ];
    __shared__ float sbv;

    const int tid = threadIdx.x;
    for (int j = tid; j < 32 * NQ; j += blockDim.x) {
        int k2 = j / NQ, q = j % NQ;
        sW1p[2 * j]     = W1[(2 * k2) * NQ + q];
        sW1p[2 * j + 1] = W1[(2 * k2 + 1) * NQ + q];
    }
    for (int i = tid; i < PRE; i += blockDim.x)      sb1[i] = b1[i];
    for (int i = tid; i < NQ * PRE; i += blockDim.x) sW2[i] = W2[i];
    if (tid < NQ) sb2[tid] = b2[tid];
    if (tid < NL * NQ) {
        float s, c;
        sincosf(0.5f * qw[tid], &s, &c);
        sqC[2 * tid] = c;  sqC[2 * tid + 1] = c;
        sqS[2 * tid] = s;  sqS[2 * tid + 1] = s;
        sqN[2 * tid] = -s; sqN[2 * tid + 1] = -s;
    }
    if (tid < NA * NQ) sWp[tid] = Wp[tid];
    if (tid < NA)      sbp[tid] = bp[tid];
    if (tid < NQ)      sWv[tid] = Wv[tid];
    if (tid == 0)      sbv = bv[0];
    __syncthreads();

    const int b = blockIdx.x * blockDim.x + tid;
    if (b >= B) return;

    // ---------------- pre-net (packed over hidden pairs / k pairs) ---------
    float xi[NQ];
    {
        const float2* xr = reinterpret_cast<const float2*>(x + (size_t)b * NQ);
        float2 v0 = xr[0], v1 = xr[1], v2 = xr[2];
        xi[0] = v0.x; xi[1] = v0.y; xi[2] = v1.x;
        xi[3] = v1.y; xi[4] = v2.x; xi[5] = v2.y;
    }
    u64 XI[NQ];
#pragma unroll
    for (int q = 0; q < NQ; ++q) XI[q] = pk(xi[q], xi[q]);

    u64 acc[NQ];
#pragma unroll
    for (int j = 0; j < NQ; ++j) acc[j] = pk(0.0f, 0.0f);

#pragma unroll
    for (int k2 = 0; k2 < 32; ++k2) {
        u64 h = *reinterpret_cast<const u64*>(sb1 + 2 * k2);
#pragma unroll
        for (int q = 0; q < NQ; ++q)
            h = fma2(*reinterpret_cast<const u64*>(sW1p + 2 * (k2 * NQ + q)), XI[q], h);
        float hl = fmaxf(f2lo(h), 0.0f);
        float hh = fmaxf(f2hi(h), 0.0f);
        u64 hr = pk(hl, hh);
#pragma unroll
        for (int j = 0; j < NQ; ++j)
            acc[j] = fma2(*reinterpret_cast<const u64*>(sW2 + j * PRE + 2 * k2), hr, acc[j]);
    }
    float xp[NQ];
#pragma unroll
    for (int j = 0; j < NQ; ++j)
        xp[j] = fmaxf(f2lo(acc[j]) + f2hi(acc[j]) + sb2[j], 0.0f);

    // ---------------- angle embedding (outer product) -----------------------
    float ec[NQ], es[NQ];
#pragma unroll
    for (int q = 0; q < NQ; ++q) __sincosf(0.5f * xp[q], &es[q], &ec[q]);

    float low[32];
    low[0] = ec[0];
    low[1] = es[0];
#pragma unroll
    for (int q = 1; q < 5; ++q) {
        const int sz = 1 << q;
#pragma unroll
        for (int i = 0; i < 32; ++i) {
            if (i < sz) {
                low[i | sz] = low[i] * es[q];
                low[i]      = low[i] * ec[q];
            }
        }
    }
    float st[NS];
#pragma unroll
    for (int i = 0; i < 32; ++i) {
        st[i]      = low[i] * ec[5];
        st[i + 32] = low[i] * es[5];
    }

    // ---------------- 4 entangling layers -----------------------------------
#pragma unroll
    for (int l = 0; l < NL; ++l) {
        // CNOT ring: compile-time permutation (register renames)
#pragma unroll
        for (int i = 0; i < NQ; ++i) {
            const int cb = 1 << i;
            const int tb = 1 << ((i + 1) % NQ);
#pragma unroll
            for (int idx = 0; idx < NS; ++idx) {
                if ((idx & cb) && !(idx & tb)) {
                    float tmp = st[idx];
                    st[idx] = st[idx | tb];
                    st[idx | tb] = tmp;
                }
            }
        }
        // RY per qubit, two butterflies packed per f32x2 op
#pragma unroll
        for (int i = 0; i < NQ; ++i) {
            const int t = l * NQ + i;
            const u64 C   = *reinterpret_cast<const u64*>(sqC + 2 * t);
            const u64 S   = *reinterpret_cast<const u64*>(sqS + 2 * t);
            const u64 NSg = *reinterpret_cast<const u64*>(sqN + 2 * t);
            const int qb = 1 << i;
            const int sb = (i == 5) ? 1 : 32;   // sibling bit for lane pairing
#pragma unroll
            for (int base = 0; base < NS; ++base) {
                if (!(base & (qb | sb))) {
                    bfly2(C, S, NSg,
                          st[base],      st[base | qb],
                          st[base | sb], st[base | sb | qb]);
                }
            }
        }
    }

    // ---------------- measurement: hierarchical marginal folding ------------
    float s0[32];
    u64 D0 = pk(0.f, 0.f), D1 = pk(0.f, 0.f), D2 = pk(0.f, 0.f), D3 = pk(0.f, 0.f);
#pragma unroll
    for (int i = 0; i < 32; ++i) {
        u64 Si = pk(st[i], st[i + 32]);
        u64 Pi = mul2(Si, Si);
        if ((i & 3) == 0)      D0 = add2(D0, Pi);
        else if ((i & 3) == 1) D1 = add2(D1, Pi);
        else if ((i & 3) == 2) D2 = add2(D2, Pi);
        else                   D3 = add2(D3, Pi);
        s0[i] = f2lo(Pi) + f2hi(Pi);
    }
    u64 D = add2(add2(D0, D1), add2(D2, D3));
    float z[NQ];
    z[5] = f2lo(D) - f2hi(D);

    float s1[16];
    {
        float zz = 0.f;
#pragma unroll
        for (int i = 0; i < 16; ++i) {
            s1[i] = s0[2 * i] + s0[2 * i + 1];
            zz   += s0[2 * i] - s0[2 * i + 1];
        }
        z[0] = zz;
    }
    float s2[8];
    {
        float zz = 0.f;
#pragma unroll
        for (int i = 0; i < 8; ++i) {
            s2[i] = s1[2 * i] + s1[2 * i + 1];
            zz   += s1[2 * i] - s1[2 * i + 1];
        }
        z[1] = zz;
    }
    float s3[4];
    {
        float zz = 0.f;
#pragma unroll
        for (int i = 0; i < 4; ++i) {
            s3[i] = s2[2 * i] + s2[2 * i + 1];
            zz   += s2[2 * i] - s2[2 * i + 1];
        }
        z[2] = zz;
    }
    float s4[2];
    {
        float zz = 0.f;
#pragma unroll
        for (int i = 0; i < 2; ++i) {
            s4[i] = s3[2 * i] + s3[2 * i + 1];
            zz   += s3[2 * i] - s3[2 * i + 1];
        }
        z[3] = zz;
    }
    z[4] = s4[0] - s4[1];

    // ---------------- heads --------------------------------------------------
    float logits[NA];
#pragma unroll
    for (int a = 0; a < NA; ++a) {
        float L = sbp[a];
#pragma unroll
        for (int q = 0; q < NQ; ++q) L = fmaf(sWp[a * NQ + q], z[q], L);
        logits[a] = L;
    }
    float m = fmaxf(fmaxf(logits[0], logits[1]), fmaxf(logits[2], logits[3]));
    float e[NA], sum = 0.0f;
#pragma unroll
    for (int a = 0; a < NA; ++a) { e[a] = __expf(logits[a] - m); sum += e[a]; }
    const float inv = __fdividef(1.0f, sum);

    float4 pol;
    pol.x = e[0] * inv;
    pol.y = e[1] * inv;
    pol.z = e[2] * inv;
    pol.w = e[3] * inv;
    reinterpret_cast<float4*>(out_policy)[b] = pol;

    float val = sbv;
#pragma unroll
    for (int q = 0; q < NQ; ++q) val = fmaf(sWv[q], z[q], val);
    out_value[b] = val;
}

extern "C" void kernel_launch(void* const* d_in, const int* in_sizes, int n_in,
                              void* d_out, int out_size) {
    const float* x  = (const float*)d_in[0];
    const float* W1 = (const float*)d_in[1];
    const float* b1 = (const float*)d_in[2];
    const float* W2 = (const float*)d_in[3];
    const float* b2 = (const float*)d_in[4];
    const float* qw = (const float*)d_in[5];
    const float* Wp = (const float*)d_in[6];
    const float* bp = (const float*)d_in[7];
    const float* Wv = (const float*)d_in[8];
    const float* bv = (const float*)d_in[9];

    const int B = in_sizes[0] / NQ;
    float* out_policy = (float*)d_out;
    float* out_value  = (float*)d_out + (size_t)B * NA;

    const int threads = 128;
    const int blocks = (B + threads - 1) / threads;
    qpolicy_kernel<<<blocks, threads>>>(x, W1, b1, W2, b2, qw, Wp, bp, Wv, bv,
                                        out_policy, out_value, B);
}

// round 3
// speedup vs baseline: 1.0113x; 1.0113x over previous
#include <cuda_runtime.h>
#include <math.h>

#define NQ 6
#define NL 4
#define NA 4
#define PRE 64
#define NS 64

typedef unsigned long long u64;

// ---- f32x2 packed helpers (persistently packed; lanes = two samples) ------
__device__ __forceinline__ u64 pk(float lo_, float hi_) {
    u64 r; asm("mov.b64 %0, {%1, %2};" : "=l"(r) : "f"(lo_), "f"(hi_)); return r;
}
__device__ __forceinline__ void upk(u64 v, float &lo_, float &hi_) {
    asm("mov.b64 {%0, %1}, %2;" : "=f"(lo_), "=f"(hi_) : "l"(v));
}
__device__ __forceinline__ u64 fma2(u64 a, u64 b, u64 c) {
    u64 d; asm("fma.rn.f32x2 %0, %1, %2, %3;" : "=l"(d) : "l"(a), "l"(b), "l"(c)); return d;
}
__device__ __forceinline__ u64 mul2(u64 a, u64 b) {
    u64 d; asm("mul.rn.f32x2 %0, %1, %2;" : "=l"(d) : "l"(a), "l"(b)); return d;
}
__device__ __forceinline__ u64 add2(u64 a, u64 b) {
    u64 d; asm("add.rn.f32x2 %0, %1, %2;" : "=l"(d) : "l"(a), "l"(b)); return d;
}
__device__ __forceinline__ u64 sub2(u64 a, u64 b) {
    u64 d; asm("sub.rn.f32x2 %0, %1, %2;" : "=l"(d) : "l"(a), "l"(b)); return d;
}
__device__ __forceinline__ u64 relu2(u64 v) {
    float a, b; upk(v, a, b);
    return pk(fmaxf(a, 0.0f), fmaxf(b, 0.0f));
}
__device__ __forceinline__ u64 lds64(const float2* p) {
    return *reinterpret_cast<const u64*>(p);
}

__global__ void __launch_bounds__(128) qpolicy_kernel(
    const float* __restrict__ x,
    const float* __restrict__ W1, const float* __restrict__ b1,
    const float* __restrict__ W2, const float* __restrict__ b2,
    const float* __restrict__ qw,
    const float* __restrict__ Wp, const float* __restrict__ bp,
    const float* __restrict__ Wv, const float* __restrict__ bv,
    float* __restrict__ out_policy, float* __restrict__ out_value,
    int NT)   // NT = number of threads = B/2
{
    // All weights duplicated into both f32x2 lanes: LDS.64/128 -> packed operand
    __shared__ __align__(16) float2 sW1d[PRE][8];   // [k][0..5]=W1[k][q] dup, [6]=b1[k] dup, [7] pad
    __shared__ __align__(16) float2 sW2d[PRE][6];   // [k][j] = W2[j][k] dup
    __shared__ __align__(16) float2 sb2d[NQ];
    __shared__ __align__(16) float2 sqCd[NL * NQ], sqSd[NL * NQ], sqNd[NL * NQ];
    __shared__ __align__(16) float2 sWpd[NA * NQ];
    __shared__ __align__(16) float2 sbpd[NA];
    __shared__ __align__(16) float2 sWvd[NQ];
    __shared__ __align__(16) float2 sbvd;

    const int tid = threadIdx.x;
    for (int i = tid; i < PRE * NQ; i += blockDim.x) {
        int k = i / NQ, q = i % NQ;
        float w = W1[i];
        sW1d[k][q] = make_float2(w, w);
        float w2 = W2[q * PRE + k];      // W2 is (NQ, PRE)
        sW2d[k][q] = make_float2(w2, w2);
    }
    if (tid < PRE) { float v = b1[tid]; sW1d[tid][6] = make_float2(v, v); }
    if (tid < NQ)  { float v = b2[tid]; sb2d[tid] = make_float2(v, v); }
    if (tid < NL * NQ) {
        float s, c;
        sincosf(0.5f * qw[tid], &s, &c);
        sqCd[tid] = make_float2(c, c);
        sqSd[tid] = make_float2(s, s);
        sqNd[tid] = make_float2(-s, -s);
    }
    if (tid < NA * NQ) { float v = Wp[tid]; sWpd[tid] = make_float2(v, v); }
    if (tid < NA)      { float v = bp[tid]; sbpd[tid] = make_float2(v, v); }
    if (tid < NQ)      { float v = Wv[tid]; sWvd[tid] = make_float2(v, v); }
    if (tid == 0)      { float v = bv[0];   sbvd = make_float2(v, v); }
    __syncthreads();

    const int t = blockIdx.x * blockDim.x + tid;
    if (t >= NT) return;

    // ---------------- load two samples (12 consecutive floats) --------------
    const float4* xr = reinterpret_cast<const float4*>(x + (size_t)t * 12);
    float4 v0 = xr[0], v1 = xr[1], v2 = xr[2];
    u64 XI[NQ];
    XI[0] = pk(v0.x, v1.z);
    XI[1] = pk(v0.y, v1.w);
    XI[2] = pk(v0.z, v2.x);
    XI[3] = pk(v0.w, v2.y);
    XI[4] = pk(v1.x, v2.z);
    XI[5] = pk(v1.y, v2.w);

    // ---------------- pre-net MLP (fully packed) ----------------------------
    u64 acc[NQ];
#pragma unroll
    for (int j = 0; j < NQ; ++j) acc[j] = lds64(&sb2d[j]);

#pragma unroll
    for (int k = 0; k < PRE; ++k) {
        const ulonglong2* wq = reinterpret_cast<const ulonglong2*>(&sW1d[k][0]);
        u64 h = lds64(&sW1d[k][6]);                 // bias dup
        ulonglong2 p01 = wq[0];
        h = fma2(p01.x, XI[0], h);
        h = fma2(p01.y, XI[1], h);
        ulonglong2 p23 = wq[1];
        h = fma2(p23.x, XI[2], h);
        h = fma2(p23.y, XI[3], h);
        ulonglong2 p45 = wq[2];
        h = fma2(p45.x, XI[4], h);
        h = fma2(p45.y, XI[5], h);
        h = relu2(h);
        const ulonglong2* w2 = reinterpret_cast<const ulonglong2*>(&sW2d[k][0]);
        ulonglong2 a01 = w2[0];
        acc[0] = fma2(a01.x, h, acc[0]);
        acc[1] = fma2(a01.y, h, acc[1]);
        ulonglong2 a23 = w2[1];
        acc[2] = fma2(a23.x, h, acc[2]);
        acc[3] = fma2(a23.y, h, acc[3]);
        ulonglong2 a45 = w2[2];
        acc[4] = fma2(a45.x, h, acc[4]);
        acc[5] = fma2(a45.y, h, acc[5]);
    }

    // ---------------- angle embedding ---------------------------------------
    u64 ECP[NQ], ESP[NQ];
#pragma unroll
    for (int j = 0; j < NQ; ++j) {
        float a0, a1;
        upk(relu2(acc[j]), a0, a1);
        float s0, c0, s1, c1;
        __sincosf(0.5f * a0, &s0, &c0);
        __sincosf(0.5f * a1, &s1, &c1);
        ECP[j] = pk(c0, c1);
        ESP[j] = pk(s0, s1);
    }

    u64 P[NS];
    P[0] = ECP[0];
    P[1] = ESP[0];
#pragma unroll
    for (int q = 1; q < NQ; ++q) {
        const int sz = 1 << q;
#pragma unroll
        for (int i = 0; i < NS; ++i) {
            if (i < sz) {
                P[i | sz] = mul2(P[i], ESP[q]);
                P[i]      = mul2(P[i], ECP[q]);
            }
        }
    }

    // ---------------- 4 entangling layers (all packed, CNOTs = renames) -----
#pragma unroll
    for (int l = 0; l < NL; ++l) {
#pragma unroll
        for (int i = 0; i < NQ; ++i) {
            const int cb = 1 << i;
            const int tb = 1 << ((i + 1) % NQ);
#pragma unroll
            for (int idx = 0; idx < NS; ++idx) {
                if ((idx & cb) && !(idx & tb)) {
                    u64 tmp = P[idx];
                    P[idx] = P[idx | tb];
                    P[idx | tb] = tmp;
                }
            }
        }
#pragma unroll
        for (int i = 0; i < NQ; ++i) {
            const int tt = l * NQ + i;
            const u64 C  = lds64(&sqCd[tt]);
            const u64 S  = lds64(&sqSd[tt]);
            const u64 Ng = lds64(&sqNd[tt]);
            const int qb = 1 << i;
#pragma unroll
            for (int base = 0; base < NS; ++base) {
                if (!(base & qb)) {
                    u64 A = P[base];
                    u64 B = P[base | qb];
                    P[base]      = fma2(C, A, mul2(Ng, B));
                    P[base | qb] = fma2(S, A, mul2(C, B));
                }
            }
        }
    }

    // ---------------- measurement (packed marginal folding) -----------------
    u64 z[NQ];
    u64 pr[NS];
#pragma unroll
    for (int i = 0; i < NS; ++i) pr[i] = mul2(P[i], P[i]);

    // fold bit0
    u64 s1[32];
    {
        u64 za = pk(0.f, 0.f), zb = pk(0.f, 0.f);
#pragma unroll
        for (int i = 0; i < 32; ++i) {
            u64 e = pr[2 * i], o = pr[2 * i + 1];
            s1[i] = add2(e, o);
            u64 d = sub2(e, o);
            if (i & 1) zb = add2(zb, d); else za = add2(za, d);
        }
        z[0] = add2(za, zb);
    }
    u64 s2[16];
    {
        u64 za = pk(0.f, 0.f), zb = pk(0.f, 0.f);
#pragma unroll
        for (int i = 0; i < 16; ++i) {
            u64 e = s1[2 * i], o = s1[2 * i + 1];
            s2[i] = add2(e, o);
            u64 d = sub2(e, o);
            if (i & 1) zb = add2(zb, d); else za = add2(za, d);
        }
        z[1] = add2(za, zb);
    }
    u64 s3[8];
    {
        u64 zz = pk(0.f, 0.f);
#pragma unroll
        for (int i = 0; i < 8; ++i) {
            u64 e = s2[2 * i], o = s2[2 * i + 1];
            s3[i] = add2(e, o);
            zz = add2(zz, sub2(e, o));
        }
        z[2] = zz;
    }
    u64 s4[4];
    {
        u64 zz = pk(0.f, 0.f);
#pragma unroll
        for (int i = 0; i < 4; ++i) {
            u64 e = s3[2 * i], o = s3[2 * i + 1];
            s4[i] = add2(e, o);
            zz = add2(zz, sub2(e, o));
        }
        z[3] = zz;
    }
    u64 s5[2];
    {
        s5[0] = add2(s4[0], s4[1]);
        s5[1] = add2(s4[2], s4[3]);
        z[4] = add2(sub2(s4[0], s4[1]), sub2(s4[2], s4[3]));
    }
    z[5] = sub2(s5[0], s5[1]);

    // ---------------- heads (packed GEMVs, scalar softmax) ------------------
    u64 L[NA];
#pragma unroll
    for (int a = 0; a < NA; ++a) {
        u64 acl = lds64(&sbpd[a]);
#pragma unroll
        for (int q = 0; q < NQ; ++q)
            acl = fma2(lds64(&sWpd[a * NQ + q]), z[q], acl);
        L[a] = acl;
    }
    float l0[NA], l1[NA];
#pragma unroll
    for (int a = 0; a < NA; ++a) upk(L[a], l0[a], l1[a]);

    {
        float m = fmaxf(fmaxf(l0[0], l0[1]), fmaxf(l0[2], l0[3]));
        float e0 = __expf(l0[0] - m), e1 = __expf(l0[1] - m);
        float e2 = __expf(l0[2] - m), e3 = __expf(l0[3] - m);
        float inv = __fdividef(1.0f, e0 + e1 + e2 + e3);
        reinterpret_cast<float4*>(out_policy)[2 * t] =
            make_float4(e0 * inv, e1 * inv, e2 * inv, e3 * inv);
    }
    {
        float m = fmaxf(fmaxf(l1[0], l1[1]), fmaxf(l1[2], l1[3]));
        float e0 = __expf(l1[0] - m), e1 = __expf(l1[1] - m);
        float e2 = __expf(l1[2] - m), e3 = __expf(l1[3] - m);
        float inv = __fdividef(1.0f, e0 + e1 + e2 + e3);
        reinterpret_cast<float4*>(out_policy)[2 * t + 1] =
            make_float4(e0 * inv, e1 * inv, e2 * inv, e3 * inv);
    }

    u64 V = lds64(&sbvd);
#pragma unroll
    for (int q = 0; q < NQ; ++q)
        V = fma2(lds64(&sWvd[q]), z[q], V);
    float va, vb; upk(V, va, vb);
    reinterpret_cast<float2*>(out_value)[t] = make_float2(va, vb);
}

extern "C" void kernel_launch(void* const* d_in, const int* in_sizes, int n_in,
                              void* d_out, int out_size) {
    const float* x  = (const float*)d_in[0];
    const float* W1 = (const float*)d_in[1];
    const float* b1 = (const float*)d_in[2];
    const float* W2 = (const float*)d_in[3];
    const float* b2 = (const float*)d_in[4];
    const float* qw = (const float*)d_in[5];
    const float* Wp = (const float*)d_in[6];
    const float* bp = (const float*)d_in[7];
    const float* Wv = (const float*)d_in[8];
    const float* bv = (const float*)d_in[9];

    const int B  = in_sizes[0] / NQ;
    const int NT = B / 2;                        // two samples per thread
    float* out_policy = (float*)d_out;
    float* out_value  = (float*)d_out + (size_t)B * NA;

    const int threads = 128;
    const int blocks = (NT + threads - 1) / threads;
    qpolicy_kernel<<<blocks, threads>>>(x, W1, b1, W2, b2, qw, Wp, bp, Wv, bv,
                                        out_policy, out_value, NT);
}

// round 4
// speedup vs baseline: 1.3853x; 1.3699x over previous
#include <cuda_runtime.h>
#include <math.h>

#define NQ 6
#define NL 4
#define NA 4
#define PRE 64
#define NS 64

typedef unsigned long long u64;

__device__ __forceinline__ u64 pk(float lo_, float hi_) {
    u64 r; asm("mov.b64 %0, {%1, %2};" : "=l"(r) : "f"(lo_), "f"(hi_)); return r;
}
__device__ __forceinline__ void upk(u64 v, float &lo_, float &hi_) {
    asm("mov.b64 {%0, %1}, %2;" : "=f"(lo_), "=f"(hi_) : "l"(v));
}
__device__ __forceinline__ u64 fma2(u64 a, u64 b, u64 c) {
    u64 d; asm("fma.rn.f32x2 %0, %1, %2, %3;" : "=l"(d) : "l"(a), "l"(b), "l"(c)); return d;
}
__device__ __forceinline__ u64 mul2(u64 a, u64 b) {
    u64 d; asm("mul.rn.f32x2 %0, %1, %2;" : "=l"(d) : "l"(a), "l"(b)); return d;
}
__device__ __forceinline__ u64 add2(u64 a, u64 b) {
    u64 d; asm("add.rn.f32x2 %0, %1, %2;" : "=l"(d) : "l"(a), "l"(b)); return d;
}
__device__ __forceinline__ u64 relu2(u64 v) {
    float a, b; upk(v, a, b);
    return pk(fmaxf(a, 0.0f), fmaxf(b, 0.0f));
}
__device__ __forceinline__ u64 lds64(const float2* p) {
    return *reinterpret_cast<const u64*>(p);
}

// Tree-sum of C elements of X spaced `stride` apart (compile-time unrolled).
template<int C>
__device__ __forceinline__ u64 tsum(const u64* X, int stride) {
    if constexpr (C == 1) return X[0];
    else return add2(tsum<C/2>(X, stride * 2), tsum<C/2>(X + stride, stride * 2));
}

__global__ void __launch_bounds__(128) qpolicy_kernel(
    const float* __restrict__ x,
    const float* __restrict__ W1, const float* __restrict__ b1,
    const float* __restrict__ W2, const float* __restrict__ b2,
    const float* __restrict__ qw,
    const float* __restrict__ Wp, const float* __restrict__ bp,
    const float* __restrict__ Wv, const float* __restrict__ bv,
    float* __restrict__ out_policy, float* __restrict__ out_value,
    int NT)   // NT = B/2 (two samples per thread, f32x2 lanes)
{
    __shared__ __align__(16) float2 sW1d[PRE][8];   // [k][0..5]=W1 dup, [6]=b1 dup
    __shared__ __align__(16) float2 sW2d[PRE][6];   // [k][j] = W2[j][k] dup
    __shared__ __align__(16) float2 sb2d[NQ];
    __shared__ __align__(16) float2 sqTd[NL * NQ];  // ( t,  t)
    __shared__ __align__(16) float2 sqNd[NL * NQ];  // (-t, -t)
    __shared__ float scC[NL * NQ];                  // scalar cos(theta/2)
    __shared__ float sG2;                           // (prod c)^2
    __shared__ __align__(16) float2 sHead[NA + 1][8]; // rows: 4 policy + 1 value
                                                    // [r][0..5]=2*G2*W, [6]=-G2*sumW, [7]=bias

    const int tid = threadIdx.x;
    for (int i = tid; i < PRE * NQ; i += blockDim.x) {
        int k = i / NQ, q = i % NQ;
        float w = W1[i];
        sW1d[k][q] = make_float2(w, w);
        float w2 = W2[q * PRE + k];
        sW2d[k][q] = make_float2(w2, w2);
    }
    if (tid < PRE) { float v = b1[tid]; sW1d[tid][6] = make_float2(v, v); }
    if (tid < NQ)  { float v = b2[tid]; sb2d[tid] = make_float2(v, v); }
    if (tid < NL * NQ) {
        float s, c;
        sincosf(0.5f * qw[tid], &s, &c);
        float t = s / c;
        scC[tid] = c;
        sqTd[tid] = make_float2(t, t);
        sqNd[tid] = make_float2(-t, -t);
    }
    __syncthreads();
    if (tid == 0) {
        float g = 1.0f;
#pragma unroll
        for (int i = 0; i < NL * NQ; ++i) g *= scC[i];
        sG2 = g * g;
    }
    __syncthreads();
    if (tid < NA + 1) {
        const float* Wr = (tid < NA) ? (Wp + tid * NQ) : Wv;
        float bias = (tid < NA) ? bp[tid] : bv[0];
        float g2 = sG2;
        float rs = 0.0f;
#pragma unroll
        for (int q = 0; q < NQ; ++q) rs += Wr[q];
#pragma unroll
        for (int q = 0; q < NQ; ++q) {
            float w = 2.0f * g2 * Wr[q];
            sHead[tid][q] = make_float2(w, w);
        }
        float wt = -g2 * rs;
        sHead[tid][6] = make_float2(wt, wt);
        sHead[tid][7] = make_float2(bias, bias);
    }
    __syncthreads();

    const int t = blockIdx.x * blockDim.x + tid;
    if (t >= NT) return;

    // ---------------- load two samples --------------------------------------
    const float4* xr = reinterpret_cast<const float4*>(x + (size_t)t * 12);
    float4 v0 = xr[0], v1 = xr[1], v2 = xr[2];
    u64 XI[NQ];
    XI[0] = pk(v0.x, v1.z);
    XI[1] = pk(v0.y, v1.w);
    XI[2] = pk(v0.z, v2.x);
    XI[3] = pk(v0.w, v2.y);
    XI[4] = pk(v1.x, v2.z);
    XI[5] = pk(v1.y, v2.w);

    // ---------------- pre-net MLP (packed) ----------------------------------
    u64 acc[NQ];
#pragma unroll
    for (int j = 0; j < NQ; ++j) acc[j] = lds64(&sb2d[j]);

#pragma unroll
    for (int k = 0; k < PRE; ++k) {
        const ulonglong2* wq = reinterpret_cast<const ulonglong2*>(&sW1d[k][0]);
        u64 h = lds64(&sW1d[k][6]);
        ulonglong2 p01 = wq[0];
        h = fma2(p01.x, XI[0], h);
        h = fma2(p01.y, XI[1], h);
        ulonglong2 p23 = wq[1];
        h = fma2(p23.x, XI[2], h);
        h = fma2(p23.y, XI[3], h);
        ulonglong2 p45 = wq[2];
        h = fma2(p45.x, XI[4], h);
        h = fma2(p45.y, XI[5], h);
        h = relu2(h);
        const ulonglong2* w2 = reinterpret_cast<const ulonglong2*>(&sW2d[k][0]);
        ulonglong2 a01 = w2[0];
        acc[0] = fma2(a01.x, h, acc[0]);
        acc[1] = fma2(a01.y, h, acc[1]);
        ulonglong2 a23 = w2[1];
        acc[2] = fma2(a23.x, h, acc[2]);
        acc[3] = fma2(a23.y, h, acc[3]);
        ulonglong2 a45 = w2[2];
        acc[4] = fma2(a45.x, h, acc[4]);
        acc[5] = fma2(a45.y, h, acc[5]);
    }

    // ---------------- angle embedding ---------------------------------------
    u64 ECP[NQ], ESP[NQ];
#pragma unroll
    for (int j = 0; j < NQ; ++j) {
        float a0, a1;
        upk(relu2(acc[j]), a0, a1);
        float s0, c0, s1c, c1;
        __sincosf(0.5f * a0, &s0, &c0);
        __sincosf(0.5f * a1, &s1c, &c1);
        ECP[j] = pk(c0, c1);
        ESP[j] = pk(s0, s1c);
    }

    u64 P[NS];
    P[0] = ECP[0];
    P[1] = ESP[0];
#pragma unroll
    for (int q = 1; q < NQ; ++q) {
        const int sz = 1 << q;
#pragma unroll
        for (int i = 0; i < NS; ++i) {
            if (i < sz) {
                P[i | sz] = mul2(P[i], ESP[q]);
                P[i]      = mul2(P[i], ECP[q]);
            }
        }
    }

    // ---------------- 4 entangling layers: tan-form gates (2 FMA/butterfly) -
#pragma unroll
    for (int l = 0; l < NL; ++l) {
        // CNOT ring = compile-time register renames
#pragma unroll
        for (int i = 0; i < NQ; ++i) {
            const int cb = 1 << i;
            const int tb = 1 << ((i + 1) % NQ);
#pragma unroll
            for (int idx = 0; idx < NS; ++idx) {
                if ((idx & cb) && !(idx & tb)) {
                    u64 tmp = P[idx];
                    P[idx] = P[idx | tb];
                    P[idx | tb] = tmp;
                }
            }
        }
        // RY in tan form: a0' = a0 - t*a1; a1' = t*a0 + a1 (scale c deferred)
#pragma unroll
        for (int i = 0; i < NQ; ++i) {
            const int g = l * NQ + i;
            const u64 Tt = lds64(&sqTd[g]);
            const u64 Nt = lds64(&sqNd[g]);
            const int qb = 1 << i;
#pragma unroll
            for (int base = 0; base < NS; ++base) {
                if (!(base & qb)) {
                    u64 A = P[base];
                    u64 B = P[base | qb];
                    P[base]      = fma2(Nt, B, A);
                    P[base | qb] = fma2(Tt, A, B);
                }
            }
        }
    }

    // ---------------- measurement: E_q (bit_q = 0 mass) and total T ---------
    u64 pr[NS];
#pragma unroll
    for (int i = 0; i < NS; ++i) pr[i] = mul2(P[i], P[i]);

    u64 F[7];   // features: E0..E5, T
    u64 A1[32];
#pragma unroll
    for (int i = 0; i < 32; ++i) A1[i] = add2(pr[2 * i], pr[2 * i + 1]);
    F[0] = tsum<32>(pr, 2);
    u64 A2[16];
#pragma unroll
    for (int i = 0; i < 16; ++i) A2[i] = add2(A1[2 * i], A1[2 * i + 1]);
    F[1] = tsum<16>(A1, 2);
    u64 A3[8];
#pragma unroll
    for (int i = 0; i < 8; ++i) A3[i] = add2(A2[2 * i], A2[2 * i + 1]);
    F[2] = tsum<8>(A2, 2);
    u64 A4[4];
#pragma unroll
    for (int i = 0; i < 4; ++i) A4[i] = add2(A3[2 * i], A3[2 * i + 1]);
    F[3] = tsum<4>(A3, 2);
    u64 A5[2];
    A5[0] = add2(A4[0], A4[1]);
    A5[1] = add2(A4[2], A4[3]);
    F[4] = add2(A4[0], A4[2]);
    F[5] = A5[0];
    F[6] = add2(A5[0], A5[1]);   // T

    // ---------------- heads: logits[r] = sum_q W'[r][q]*F[q] + bias ---------
    u64 L[NA + 1];
#pragma unroll
    for (int r = 0; r < NA + 1; ++r) {
        u64 a = lds64(&sHead[r][7]);
#pragma unroll
        for (int q = 0; q < 7; ++q)
            a = fma2(lds64(&sHead[r][q]), F[q], a);
        L[r] = a;
    }
    float l0[NA], l1[NA];
#pragma unroll
    for (int a = 0; a < NA; ++a) upk(L[a], l0[a], l1[a]);

    {
        float m = fmaxf(fmaxf(l0[0], l0[1]), fmaxf(l0[2], l0[3]));
        float e0 = __expf(l0[0] - m), e1 = __expf(l0[1] - m);
        float e2 = __expf(l0[2] - m), e3 = __expf(l0[3] - m);
        float inv = __fdividef(1.0f, e0 + e1 + e2 + e3);
        reinterpret_cast<float4*>(out_policy)[2 * t] =
            make_float4(e0 * inv, e1 * inv, e2 * inv, e3 * inv);
    }
    {
        float m = fmaxf(fmaxf(l1[0], l1[1]), fmaxf(l1[2], l1[3]));
        float e0 = __expf(l1[0] - m), e1 = __expf(l1[1] - m);
        float e2 = __expf(l1[2] - m), e3 = __expf(l1[3] - m);
        float inv = __fdividef(1.0f, e0 + e1 + e2 + e3);
        reinterpret_cast<float4*>(out_policy)[2 * t + 1] =
            make_float4(e0 * inv, e1 * inv, e2 * inv, e3 * inv);
    }

    float va, vb; upk(L[NA], va, vb);
    reinterpret_cast<float2*>(out_value)[t] = make_float2(va, vb);
}

extern "C" void kernel_launch(void* const* d_in, const int* in_sizes, int n_in,
                              void* d_out, int out_size) {
    const float* x  = (const float*)d_in[0];
    const float* W1 = (const float*)d_in[1];
    const float* b1 = (const float*)d_in[2];
    const float* W2 = (const float*)d_in[3];
    const float* b2 = (const float*)d_in[4];
    const float* qw = (const float*)d_in[5];
    const float* Wp = (const float*)d_in[6];
    const float* bp = (const float*)d_in[7];
    const float* Wv = (const float*)d_in[8];
    const float* bv = (const float*)d_in[9];

    const int B  = in_sizes[0] / NQ;
    const int NT = B / 2;
    float* out_policy = (float*)d_out;
    float* out_value  = (float*)d_out + (size_t)B * NA;

    const int threads = 128;
    const int blocks = (NT + threads - 1) / threads;
    qpolicy_kernel<<<blocks, threads>>>(x, W1, b1, W2, b2, qw, Wp, bp, Wv, bv,
                                        out_policy, out_value, NT);
}